// round 12
// baseline (speedup 1.0000x reference)
#include <cuda_runtime.h>
#include <cuda_bf16.h>

#define N 128
#define K 64
#define LLRMAX 100.0f
#define NPAT 2080   // 64 singles + 2016 pairs (t=2)

typedef unsigned long long u64;
typedef unsigned int u32;
typedef unsigned short u16;

__device__ __forceinline__ u32 mono(float s) {
    u32 u = __float_as_uint(s);
    return (u & 0x80000000u) ? ~u : (u | 0x80000000u);
}

__device__ __forceinline__ void decode_pair(int r, int& pi, int& pj) {
    int i = (int)((127.0f - sqrtf(16129.0f - 8.0f * (float)r)) * 0.5f);
    if (i < 0) i = 0; if (i > 62) i = 62;
    while (i * (127 - i) / 2 > r) i--;
    while ((i + 1) * (126 - i) / 2 <= r) i++;
    pi = i;
    pj = i + 1 + (r - i * (127 - i) / 2);
}

__global__ __launch_bounds__(256, 1)
void osd_kernel(const float* __restrict__ llrs,
                const float* __restrict__ gm,
                float* __restrict__ out)
{
    const int b    = blockIdx.x;
    const int tid  = threadIdx.x;
    const int lane = tid & 31;
    const int warp = tid >> 5;

    __shared__ __align__(16) float sLLR[N];
    __shared__ __align__(16) u64   sKey[N];
    __shared__ __align__(16) int   sIdxArr[N];
    __shared__ int   sRankArr[N];
    __shared__ u64   sP[K];                  // packed P rows (orig col order)
    __shared__ u32   sW[4][K];               // permuted-row quarters
    __shared__ u64   rloS[K], rhiS[K];       // reduced GF(2) rows
    __shared__ int   sPivArr[K];
    __shared__ u64   sPmLo, sPmHi;
    __shared__ __align__(16) int sMrbS[N];
    __shared__ float sLlrMrbS[N];
    __shared__ int   sTotS[N];
    __shared__ __align__(8) u64 sPPv[K];     // parity rows (4 u16 pieces each)
    __shared__ unsigned char sUS[K];
    __shared__ float sSm[K];
    __shared__ float sLUT[8 * 256];
    __shared__ u64   sRed[8];

    // ===== Phase A: tid<128 loads llr+keys; warps 4-7 issue gm LDGs (in flight across bar) =====
    float f0[16], f1[16];
    if (tid < 128) {
        float x = llrs[b * N + tid];
        x = fminf(fmaxf(x, -LLRMAX), LLRMAX);
        sLLR[tid] = x;
        u32 ab = __float_as_uint(fabsf(x));
        // ascending key => descending |llr|, tie -> smaller original idx
        sKey[tid] = (((u64)(ab ^ 0xFFFFFFFFu)) << 8) | (u32)tid;
    } else {
        int r0 = (warp - 4) << 4;
        #pragma unroll
        for (int q = 0; q < 16; q++) {
            f0[q] = gm[(r0 + q) * N + 64 + lane];
            f1[q] = gm[(r0 + q) * N + 96 + lane];
        }
    }
    __syncthreads();   // bar1

    // ===== Rank sort (warps 0-3) overlapped with gm ballot-pack (warps 4-7) =====
    if (tid < 128) {
        u64 my = sKey[tid];
        const ulonglong2* kp = (const ulonglong2*)sKey;
        int cnt = 0;
        #pragma unroll
        for (int o = 0; o < 64; o++) {
            ulonglong2 kk = kp[o];
            cnt += (int)(kk.x < my) + (int)(kk.y < my);
        }
        sIdxArr[cnt]  = tid;
        sRankArr[tid] = cnt;
    } else {
        int r0 = (warp - 4) << 4;
        #pragma unroll
        for (int q = 0; q < 16; q++) {
            u32 b0 = __ballot_sync(0xFFFFFFFFu, f0[q] != 0.0f);
            u32 b1 = __ballot_sync(0xFFFFFFFFu, f1[q] != 0.0f);
            if (lane == 0) sP[r0 + q] = (u64)b0 | ((u64)b1 << 32);
        }
    }
    __syncthreads();   // bar2

    // ===== Phase B: permuted rows, 4 threads/row (u32 quarters) =====
    {
        int row = tid & 63, q = tid >> 6;      // q in 0..3
        u64 myP = sP[row];
        u32 w = 0u;
        const int4* v = (const int4*)(sIdxArr + (q << 5));
        #pragma unroll
        for (int t = 0; t < 8; t++) {
            int4 c4 = v[t];
            int j = t << 2;
            u32 b0 = ((u32)(c4.x - 64) < 64u) ? (u32)((myP >> (c4.x - 64)) & 1ull) : 0u;
            u32 b1 = ((u32)(c4.y - 64) < 64u) ? (u32)((myP >> (c4.y - 64)) & 1ull) : 0u;
            u32 b2 = ((u32)(c4.z - 64) < 64u) ? (u32)((myP >> (c4.z - 64)) & 1ull) : 0u;
            u32 b3 = ((u32)(c4.w - 64) < 64u) ? (u32)((myP >> (c4.w - 64)) & 1ull) : 0u;
            w |= (b0 << j) | (b1 << (j + 1)) | (b2 << (j + 2)) | (b3 << (j + 3));
        }
        int rk = sRankArr[row];                // identity column of this row
        if ((rk >> 5) == q) w |= 1u << (rk & 31);
        sW[q][row] = w;
    }
    __syncthreads();   // bar3

    // ===== Phase C: blocked GF(2) elimination (warp0, 4 rows/lane, 16 lanes) =====
    if (warp == 0 && lane < 16) {
        u64 rl[4], rh[4];
        #pragma unroll
        for (int m = 0; m < 4; m++) {
            int r = 4 * lane + m;
            rl[m] = (u64)sW[0][r] | ((u64)sW[1][r] << 32);
            rh[m] = (u64)sW[2][r] | ((u64)sW[3][r] << 32);
        }
        u64 pmLo = 0ull, pmHi = 0ull;
        #pragma unroll 1
        for (int bi = 0; bi < 16; bi++) {
            u32 ppack = 0u;
            if (lane == bi) {
                // intra-block mutual elimination (in-register, no shfl)
                #pragma unroll
                for (int m = 0; m < 4; m++) {
                    int p = rl[m] ? (__ffsll((long long)rl[m]) - 1)
                                  : 64 + (__ffsll((long long)rh[m]) - 1);
                    ppack |= (u32)p << (m * 8);
                    int sh = p & 63;
                    bool pl = (p < 64);
                    u64 bl = rl[m], bh = rh[m];
                    #pragma unroll
                    for (int mm = 0; mm < 4; mm++) {
                        if (mm == m) continue;
                        bool hit = ((pl ? rl[mm] : rh[mm]) >> sh) & 1ull;
                        if (hit) { rl[mm] ^= bl; rh[mm] ^= bh; }
                    }
                }
            }
            // broadcast 4 pivot rows + packed pivots
            u64 plo0 = __shfl_sync(0xFFFFu, rl[0], bi);
            u64 phi0 = __shfl_sync(0xFFFFu, rh[0], bi);
            u64 plo1 = __shfl_sync(0xFFFFu, rl[1], bi);
            u64 phi1 = __shfl_sync(0xFFFFu, rh[1], bi);
            u64 plo2 = __shfl_sync(0xFFFFu, rl[2], bi);
            u64 phi2 = __shfl_sync(0xFFFFu, rh[2], bi);
            u64 plo3 = __shfl_sync(0xFFFFu, rl[3], bi);
            u64 phi3 = __shfl_sync(0xFFFFu, rh[3], bi);
            ppack    = __shfl_sync(0xFFFFu, ppack, bi);

            int p0 = ppack & 0xFF, p1 = (ppack >> 8) & 0xFF;
            int p2 = (ppack >> 16) & 0xFF, p3 = (ppack >> 24) & 0xFF;

            if (lane == 0) {
                sPivArr[4 * bi]     = p0;
                sPivArr[4 * bi + 1] = p1;
                sPivArr[4 * bi + 2] = p2;
                sPivArr[4 * bi + 3] = p3;
                if (p0 < 64) pmLo |= 1ull << p0; else pmHi |= 1ull << (p0 - 64);
                if (p1 < 64) pmLo |= 1ull << p1; else pmHi |= 1ull << (p1 - 64);
                if (p2 < 64) pmLo |= 1ull << p2; else pmHi |= 1ull << (p2 - 64);
                if (p3 < 64) pmLo |= 1ull << p3; else pmHi |= 1ull << (p3 - 64);
            }
            if (lane != bi) {
                #pragma unroll
                for (int mm = 0; mm < 4; mm++) {
                    bool h;
                    h = (((p0 < 64) ? rl[mm] : rh[mm]) >> (p0 & 63)) & 1ull;
                    if (h) { rl[mm] ^= plo0; rh[mm] ^= phi0; }
                    h = (((p1 < 64) ? rl[mm] : rh[mm]) >> (p1 & 63)) & 1ull;
                    if (h) { rl[mm] ^= plo1; rh[mm] ^= phi1; }
                    h = (((p2 < 64) ? rl[mm] : rh[mm]) >> (p2 & 63)) & 1ull;
                    if (h) { rl[mm] ^= plo2; rh[mm] ^= phi2; }
                    h = (((p3 < 64) ? rl[mm] : rh[mm]) >> (p3 & 63)) & 1ull;
                    if (h) { rl[mm] ^= plo3; rh[mm] ^= phi3; }
                }
            }
        }
        #pragma unroll
        for (int m = 0; m < 4; m++) {
            int r = 4 * lane + m;
            rloS[r] = rl[m];
            rhiS[r] = rh[m];
        }
        if (lane == 0) { sPmLo = pmLo; sPmHi = pmHi; }
    }
    __syncthreads();   // bar4

    // ===== Phase D: idx_mrb + gathers (+ fused sUS / sSm) =====
    if (tid < 128) {
        int m;
        if (tid < K) {
            m = sPivArr[tid];
        } else {
            int t = tid - K;
            u64 zlo = ~sPmLo, zhi = ~sPmHi;
            int nlo = __popcll(zlo);
            u64 x; int base;
            if (t < nlo) { x = zlo; base = 0; }
            else         { x = zhi; base = 64; t -= nlo; }
            int pos = 0;
            #pragma unroll
            for (int byteI = 0; byteI < 8; byteI++) {
                u32 bb = (u32)(x >> (byteI * 8)) & 0xFFu;
                int c = __popc(bb);
                if (t < c) {
                    while (t > 0) { bb &= bb - 1; t--; }
                    pos = byteI * 8 + (__ffs(bb) - 1);
                    break;
                }
                t -= c;
            }
            m = base + pos;
        }
        sMrbS[tid] = m;
        int oc = sIdxArr[m];
        float x = sLLR[oc];
        sLlrMrbS[tid] = x;
        sTotS[tid]    = oc;
        if (tid < K) {
            int u = (x > 0.0f) ? 1 : 0;
            sUS[tid] = (unsigned char)u;
            sSm[tid] = u ? -x : x;
        }
    }
    __syncthreads();   // bar5

    // ===== Phase E1: parity pieces, 4 threads/row (u16 each) =====
    {
        int row = tid & 63, q = tid >> 6;      // q in 0..3
        u64 lo = rloS[row], hi = rhiS[row];
        u32 pr = 0u;
        int p0 = q << 4;
        const int4* v = (const int4*)(sMrbS + 64 + p0);
        #pragma unroll
        for (int t = 0; t < 4; t++) {
            int4 c4 = v[t];
            int p = t << 2;
            u32 b0 = (u32)((c4.x < 64) ? ((lo >> c4.x) & 1ull) : ((hi >> (c4.x - 64)) & 1ull));
            u32 b1 = (u32)((c4.y < 64) ? ((lo >> c4.y) & 1ull) : ((hi >> (c4.y - 64)) & 1ull));
            u32 b2 = (u32)((c4.z < 64) ? ((lo >> c4.z) & 1ull) : ((hi >> (c4.z - 64)) & 1ull));
            u32 b3 = (u32)((c4.w < 64) ? ((lo >> c4.w) & 1ull) : ((hi >> (c4.w - 64)) & 1ull));
            pr |= (b0 << p) | (b1 << (p + 1)) | (b2 << (p + 2)) | (b3 << (p + 3));
        }
        ((u16*)&sPPv[row])[q] = (u16)pr;
    }
    __syncthreads();   // bar6

    // ===== cpar: every warp reduces redundantly (no extra barrier) =====
    u64 cpar;
    {
        u64 v = (sUS[lane] ? sPPv[lane] : 0ull)
              ^ (sUS[lane + 32] ? sPPv[lane + 32] : 0ull);
        #pragma unroll
        for (int o = 16; o > 0; o >>= 1)
            v ^= __shfl_xor_sync(0xFFFFFFFFu, v, o);
        cpar = v;
    }

    // ===== Phase F: LUT build — warp-per-chunk, register DP (8 entries/thread) =====
    {
        int ci = warp;            // chunk 0..7 (uniform per warp)
        float sv[8];
        #pragma unroll
        for (int bb = 0; bb < 8; bb++) {
            int p = ci * 8 + bb;
            float x = sLlrMrbS[64 + p];               // broadcast LDS
            sv[bb] = ((cpar >> p) & 1ull) ? -x : x;
        }
        float base = 0.0f;
        #pragma unroll
        for (int bb = 0; bb < 5; bb++)
            if ((lane >> bb) & 1) base += sv[bb];
        float h5 = sv[5], h6 = sv[6], h7 = sv[7];
        float s56 = h5 + h6, s57 = h5 + h7, s67 = h6 + h7, s567 = s56 + h7;
        float hsum[8] = {0.0f, h5, h6, s56, h7, s57, s67, s567};
        float* dst = sLUT + (ci << 8) + lane;
        #pragma unroll
        for (int e = 0; e < 8; e++)
            dst[e << 5] = base + hsum[e];
    }
    __syncthreads();   // bar7

    // ===== Phase G: candidate search =====
    int id, cnt;
    if (tid < 32) { id = tid * 9;              cnt = 9; }
    else          { id = 288 + (tid - 32) * 8; cnt = 8; }

    int pi = 0, pj = 0;
    if (id >= 64 && id < NPAT) decode_pair(id - 64, pi, pj);

    float bestS = 0.0f;          // base codeword score
    int   bestId = -1;
    for (int e = 0; e < cnt && id < NPAT; e++) {
        u64 m; float S;
        if (id < 64) { m = sPPv[id];            S = sSm[id]; }
        else         { m = sPPv[pi] ^ sPPv[pj]; S = sSm[pi] + sSm[pj]; }
        #pragma unroll
        for (int cc = 0; cc < 8; cc++)
            S += sLUT[(cc << 8) | ((int)(m >> (cc * 8)) & 0xFF)];
        if (S > bestS) { bestS = S; bestId = id; }   // ids ascending -> first max kept
        id++;
        if (id == 64)     { pi = 0; pj = 1; }
        else if (id > 64) { pj++; if (pj == 64) { pi++; pj = pi + 1; } }
    }
    u64 bestKey = (((u64)mono(bestS)) << 32) | (u32)(NPAT - bestId);
    #pragma unroll
    for (int o = 16; o > 0; o >>= 1) {
        u64 other = __shfl_xor_sync(0xFFFFFFFFu, bestKey, o);
        if (other > bestKey) bestKey = other;
    }
    if (lane == 0) sRed[warp] = bestKey;
    __syncthreads();   // bar8

    // ===== Phase H: decode winner + emit =====
    if (tid < 128) {
        u64 bk = sRed[0];
        #pragma unroll
        for (int w = 1; w < 8; w++) if (sRed[w] > bk) bk = sRed[w];
        int wid2 = NPAT - (int)(bk & 0xFFFFFFFFull);   // -1 = base
        int fi = -1, fj = -1;
        if (wid2 >= 0) {
            if (wid2 < 64) fi = wid2;
            else           decode_pair(wid2 - 64, fi, fj);
        }
        int j = tid;
        int cj = (j < 64) ? (int)sUS[j] : (int)((cpar >> (j - 64)) & 1ull);
        if (j < 64) {
            if (j == fi) cj ^= 1;
            if (j == fj) cj ^= 1;
        } else {
            int p = j - 64;
            if (fi >= 0) cj ^= (int)((sPPv[fi] >> p) & 1ull);
            if (fj >= 0) cj ^= (int)((sPPv[fj] >> p) & 1ull);
        }
        out[b * N + sTotS[j]] = (float)cj;
    }
}

extern "C" void kernel_launch(void* const* d_in, const int* in_sizes, int n_in,
                              void* d_out, int out_size)
{
    const float* llrs = (const float*)d_in[0];
    const float* gm   = (const float*)d_in[1];
    float* out        = (float*)d_out;
    int bs = in_sizes[0] / N;   // 128
    osd_kernel<<<bs, 256>>>(llrs, gm, out);
}

// round 14
// speedup vs baseline: 1.2401x; 1.2401x over previous
#include <cuda_runtime.h>
#include <cuda_bf16.h>

#define N 128
#define K 64
#define LLRMAX 100.0f
#define NPAT 2080   // 64 singles + 2016 pairs (t=2)

typedef unsigned long long u64;
typedef unsigned int u32;
typedef unsigned short u16;

__device__ __forceinline__ u32 mono(float s) {
    u32 u = __float_as_uint(s);
    return (u & 0x80000000u) ? ~u : (u | 0x80000000u);
}

__device__ __forceinline__ void decode_pair(int r, int& pi, int& pj) {
    int i = (int)((127.0f - sqrtf(16129.0f - 8.0f * (float)r)) * 0.5f);
    if (i < 0) i = 0; if (i > 62) i = 62;
    while (i * (127 - i) / 2 > r) i--;
    while ((i + 1) * (126 - i) / 2 <= r) i++;
    pi = i;
    pj = i + 1 + (r - i * (127 - i) / 2);
}

__global__ __launch_bounds__(256, 1)
void osd_kernel(const float* __restrict__ llrs,
                const float* __restrict__ gm,
                float* __restrict__ out)
{
    const int b    = blockIdx.x;
    const int tid  = threadIdx.x;
    const int lane = tid & 31;
    const int warp = tid >> 5;

    __shared__ __align__(16) float sLLR[N];
    __shared__ __align__(16) u64   sKey[N];
    __shared__ __align__(16) int   sIdxArr[N];
    __shared__ int   sRankArr[N];
    __shared__ u64   sP[K];                  // packed P rows (orig col order)
    __shared__ u32   sW[4][K];               // permuted-row quarters
    __shared__ u64   rloS[K], rhiS[K];       // reduced GF(2) rows
    __shared__ int   sPivArr[K];
    __shared__ u64   sPmLo, sPmHi;
    __shared__ __align__(16) int sMrbS[N];
    __shared__ float sLlrMrbS[N];
    __shared__ int   sTotS[N];
    __shared__ __align__(8) u64 sPPv[K];     // parity rows (4 u16 pieces each)
    __shared__ unsigned char sUS[K];
    __shared__ float sSm[K];
    __shared__ float sLUT[8 * 256];
    __shared__ u64   sRed[8];

    // ===== Phase A: tid<128 loads llr+keys; warps 4-7 issue gm LDGs (fly across bar1) =====
    float f0[16], f1[16];
    if (tid < 128) {
        float x = llrs[b * N + tid];
        x = fminf(fmaxf(x, -LLRMAX), LLRMAX);
        sLLR[tid] = x;
        u32 ab = __float_as_uint(fabsf(x));
        // ascending key => descending |llr|, tie -> smaller original idx
        sKey[tid] = (((u64)(ab ^ 0xFFFFFFFFu)) << 8) | (u32)tid;
    } else {
        int r0 = (warp - 4) << 4;
        #pragma unroll
        for (int q = 0; q < 16; q++) {
            f0[q] = gm[(r0 + q) * N + 64 + lane];
            f1[q] = gm[(r0 + q) * N + 96 + lane];
        }
    }
    __syncthreads();   // bar1

    // ===== Rank sort (warps 0-3) overlapped with gm ballot-pack (warps 4-7) =====
    if (tid < 128) {
        u64 my = sKey[tid];
        const ulonglong2* kp = (const ulonglong2*)sKey;
        int cnt = 0;
        #pragma unroll
        for (int o = 0; o < 64; o++) {
            ulonglong2 kk = kp[o];
            cnt += (int)(kk.x < my) + (int)(kk.y < my);
        }
        sIdxArr[cnt]  = tid;
        sRankArr[tid] = cnt;
    } else {
        int r0 = (warp - 4) << 4;
        #pragma unroll
        for (int q = 0; q < 16; q++) {
            u32 b0 = __ballot_sync(0xFFFFFFFFu, f0[q] != 0.0f);
            u32 b1 = __ballot_sync(0xFFFFFFFFu, f1[q] != 0.0f);
            if (lane == 0) sP[r0 + q] = (u64)b0 | ((u64)b1 << 32);
        }
    }
    __syncthreads();   // bar2

    // ===== Phase B: permuted rows, 4 threads/row (u32 quarters) =====
    {
        int row = tid & 63, q = tid >> 6;      // q in 0..3
        u64 myP = sP[row];
        u32 w = 0u;
        const int4* v = (const int4*)(sIdxArr + (q << 5));
        #pragma unroll
        for (int t = 0; t < 8; t++) {
            int4 c4 = v[t];
            int j = t << 2;
            u32 b0 = ((u32)(c4.x - 64) < 64u) ? (u32)((myP >> (c4.x - 64)) & 1ull) : 0u;
            u32 b1 = ((u32)(c4.y - 64) < 64u) ? (u32)((myP >> (c4.y - 64)) & 1ull) : 0u;
            u32 b2 = ((u32)(c4.z - 64) < 64u) ? (u32)((myP >> (c4.z - 64)) & 1ull) : 0u;
            u32 b3 = ((u32)(c4.w - 64) < 64u) ? (u32)((myP >> (c4.w - 64)) & 1ull) : 0u;
            w |= (b0 << j) | (b1 << (j + 1)) | (b2 << (j + 2)) | (b3 << (j + 3));
        }
        int rk = sRankArr[row];                // identity column of this row
        if ((rk >> 5) == q) w |= 1u << (rk & 31);
        sW[q][row] = w;
    }
    __syncthreads();   // bar3

    // ===== Phase C: GF(2) elimination (warp0, rows 2l/2l+1 per lane — R7 form) =====
    if (warp == 0) {
        int r0 = 2 * lane, r1 = 2 * lane + 1;
        u64 a0lo = (u64)sW[0][r0] | ((u64)sW[1][r0] << 32);
        u64 a0hi = (u64)sW[2][r0] | ((u64)sW[3][r0] << 32);
        u64 a1lo = (u64)sW[0][r1] | ((u64)sW[1][r1] << 32);
        u64 a1hi = (u64)sW[2][r1] | ((u64)sW[3][r1] << 32);
        u64 pmLo = 0ull, pmHi = 0ull;
        #pragma unroll 1
        for (int i = 0; i < 64; i += 2) {
            int src = i >> 1;
            {   // pivot row i = a0 of lane src
                u64 plo = __shfl_sync(0xFFFFFFFFu, a0lo, src);
                u64 phi = __shfl_sync(0xFFFFFFFFu, a0hi, src);
                int p = plo ? (__ffsll((long long)plo) - 1)
                            : 64 + (__ffsll((long long)phi) - 1);
                if (lane == 0) {
                    sPivArr[i] = p;
                    if (p < 64) pmLo |= 1ull << p; else pmHi |= 1ull << (p - 64);
                }
                int sh = p & 63;
                bool h0 = (((p < 64) ? a0lo : a0hi) >> sh) & 1ull;
                bool h1 = (((p < 64) ? a1lo : a1hi) >> sh) & 1ull;
                if (h0 && lane != src)  { a0lo ^= plo; a0hi ^= phi; }
                if (h1)                 { a1lo ^= plo; a1hi ^= phi; }
            }
            {   // pivot row i+1 = a1 of lane src
                u64 plo = __shfl_sync(0xFFFFFFFFu, a1lo, src);
                u64 phi = __shfl_sync(0xFFFFFFFFu, a1hi, src);
                int p = plo ? (__ffsll((long long)plo) - 1)
                            : 64 + (__ffsll((long long)phi) - 1);
                if (lane == 0) {
                    sPivArr[i + 1] = p;
                    if (p < 64) pmLo |= 1ull << p; else pmHi |= 1ull << (p - 64);
                }
                int sh = p & 63;
                bool h0 = (((p < 64) ? a0lo : a0hi) >> sh) & 1ull;
                bool h1 = (((p < 64) ? a1lo : a1hi) >> sh) & 1ull;
                if (h0)                 { a0lo ^= plo; a0hi ^= phi; }
                if (h1 && lane != src)  { a1lo ^= plo; a1hi ^= phi; }
            }
        }
        rloS[r0] = a0lo; rhiS[r0] = a0hi;
        rloS[r1] = a1lo; rhiS[r1] = a1hi;
        if (lane == 0) { sPmLo = pmLo; sPmHi = pmHi; }
    }
    __syncthreads();   // bar4

    // ===== Phase D: idx_mrb + gathers (+ fused sUS / sSm) =====
    if (tid < 128) {
        int m;
        if (tid < K) {
            m = sPivArr[tid];
        } else {
            int t = tid - K;
            u64 zlo = ~sPmLo, zhi = ~sPmHi;
            int nlo = __popcll(zlo);
            u64 x; int base;
            if (t < nlo) { x = zlo; base = 0; }
            else         { x = zhi; base = 64; t -= nlo; }
            int pos = 0;
            #pragma unroll
            for (int byteI = 0; byteI < 8; byteI++) {
                u32 bb = (u32)(x >> (byteI * 8)) & 0xFFu;
                int c = __popc(bb);
                if (t < c) {
                    while (t > 0) { bb &= bb - 1; t--; }
                    pos = byteI * 8 + (__ffs(bb) - 1);
                    break;
                }
                t -= c;
            }
            m = base + pos;
        }
        sMrbS[tid] = m;
        int oc = sIdxArr[m];
        float x = sLLR[oc];
        sLlrMrbS[tid] = x;
        sTotS[tid]    = oc;
        if (tid < K) {
            int u = (x > 0.0f) ? 1 : 0;
            sUS[tid] = (unsigned char)u;
            sSm[tid] = u ? -x : x;
        }
    }
    __syncthreads();   // bar5

    // ===== Phase E1: parity pieces, 4 threads/row (u16 each) =====
    {
        int row = tid & 63, q = tid >> 6;      // q in 0..3
        u64 lo = rloS[row], hi = rhiS[row];
        u32 pr = 0u;
        int p0 = q << 4;
        const int4* v = (const int4*)(sMrbS + 64 + p0);
        #pragma unroll
        for (int t = 0; t < 4; t++) {
            int4 c4 = v[t];
            int p = t << 2;
            u32 b0 = (u32)((c4.x < 64) ? ((lo >> c4.x) & 1ull) : ((hi >> (c4.x - 64)) & 1ull));
            u32 b1 = (u32)((c4.y < 64) ? ((lo >> c4.y) & 1ull) : ((hi >> (c4.y - 64)) & 1ull));
            u32 b2 = (u32)((c4.z < 64) ? ((lo >> c4.z) & 1ull) : ((hi >> (c4.z - 64)) & 1ull));
            u32 b3 = (u32)((c4.w < 64) ? ((lo >> c4.w) & 1ull) : ((hi >> (c4.w - 64)) & 1ull));
            pr |= (b0 << p) | (b1 << (p + 1)) | (b2 << (p + 2)) | (b3 << (p + 3));
        }
        ((u16*)&sPPv[row])[q] = (u16)pr;
    }
    __syncthreads();   // bar6

    // ===== cpar: every warp reduces redundantly (no extra barrier) =====
    u64 cpar;
    {
        u64 v = (sUS[lane] ? sPPv[lane] : 0ull)
              ^ (sUS[lane + 32] ? sPPv[lane + 32] : 0ull);
        #pragma unroll
        for (int o = 16; o > 0; o >>= 1)
            v ^= __shfl_xor_sync(0xFFFFFFFFu, v, o);
        cpar = v;
    }

    // ===== Phase F: LUT build — warp-per-chunk, register DP (8 entries/thread) =====
    {
        int ci = warp;            // chunk 0..7 (uniform per warp)
        float sv[8];
        #pragma unroll
        for (int bb = 0; bb < 8; bb++) {
            int p = ci * 8 + bb;
            float x = sLlrMrbS[64 + p];               // broadcast LDS
            sv[bb] = ((cpar >> p) & 1ull) ? -x : x;
        }
        float base = 0.0f;
        #pragma unroll
        for (int bb = 0; bb < 5; bb++)
            if ((lane >> bb) & 1) base += sv[bb];
        float h5 = sv[5], h6 = sv[6], h7 = sv[7];
        float s56 = h5 + h6, s57 = h5 + h7, s67 = h6 + h7, s567 = s56 + h7;
        float hsum[8] = {0.0f, h5, h6, s56, h7, s57, s67, s567};
        float* dst = sLUT + (ci << 8) + lane;
        #pragma unroll
        for (int e = 0; e < 8; e++)
            dst[e << 5] = base + hsum[e];
    }
    __syncthreads();   // bar7

    // ===== Phase G: candidate search =====
    int id, cnt;
    if (tid < 32) { id = tid * 9;              cnt = 9; }
    else          { id = 288 + (tid - 32) * 8; cnt = 8; }

    int pi = 0, pj = 0;
    if (id >= 64 && id < NPAT) decode_pair(id - 64, pi, pj);

    float bestS = 0.0f;          // base codeword score
    int   bestId = -1;
    for (int e = 0; e < cnt && id < NPAT; e++) {
        u64 m; float S;
        if (id < 64) { m = sPPv[id];            S = sSm[id]; }
        else         { m = sPPv[pi] ^ sPPv[pj]; S = sSm[pi] + sSm[pj]; }
        #pragma unroll
        for (int cc = 0; cc < 8; cc++)
            S += sLUT[(cc << 8) | ((int)(m >> (cc * 8)) & 0xFF)];
        if (S > bestS) { bestS = S; bestId = id; }   // ids ascending -> first max kept
        id++;
        if (id == 64)     { pi = 0; pj = 1; }
        else if (id > 64) { pj++; if (pj == 64) { pi++; pj = pi + 1; } }
    }
    u64 bestKey = (((u64)mono(bestS)) << 32) | (u32)(NPAT - bestId);
    #pragma unroll
    for (int o = 16; o > 0; o >>= 1) {
        u64 other = __shfl_xor_sync(0xFFFFFFFFu, bestKey, o);
        if (other > bestKey) bestKey = other;
    }
    if (lane == 0) sRed[warp] = bestKey;
    __syncthreads();   // bar8

    // ===== Phase H: decode winner + emit =====
    if (tid < 128) {
        u64 bk = sRed[0];
        #pragma unroll
        for (int w = 1; w < 8; w++) if (sRed[w] > bk) bk = sRed[w];
        int wid2 = NPAT - (int)(bk & 0xFFFFFFFFull);   // -1 = base
        int fi = -1, fj = -1;
        if (wid2 >= 0) {
            if (wid2 < 64) fi = wid2;
            else           decode_pair(wid2 - 64, fi, fj);
        }
        int j = tid;
        int cj = (j < 64) ? (int)sUS[j] : (int)((cpar >> (j - 64)) & 1ull);
        if (j < 64) {
            if (j == fi) cj ^= 1;
            if (j == fj) cj ^= 1;
        } else {
            int p = j - 64;
            if (fi >= 0) cj ^= (int)((sPPv[fi] >> p) & 1ull);
            if (fj >= 0) cj ^= (int)((sPPv[fj] >> p) & 1ull);
        }
        out[b * N + sTotS[j]] = (float)cj;
    }
}

extern "C" void kernel_launch(void* const* d_in, const int* in_sizes, int n_in,
                              void* d_out, int out_size)
{
    const float* llrs = (const float*)d_in[0];
    const float* gm   = (const float*)d_in[1];
    float* out        = (float*)d_out;
    int bs = in_sizes[0] / N;   // 128
    osd_kernel<<<bs, 256>>>(llrs, gm, out);
}